// round 16
// baseline (speedup 1.0000x reference)
#include <cuda_runtime.h>
#include <cuda_bf16.h>
#include <cuda_fp8.h>
#include <cstdint>

// ---------------------------------------------------------------------------
// Problem constants
// ---------------------------------------------------------------------------
#define N_BATCH 8192
#define N_IN    784
#define N_HID   4096
#define N_OUT   10
#define KP      896      // K padded to 7 * 128 (big chunks of 128)
#define NCH     7        // big K-chunks
// real K = 784: chunks 0..5 full (8 k16 / 4 k32 steps), chunk 6: 1 k16 / 1 k32.

// ---------------------------------------------------------------------------
// Device scratch (static: no allocation allowed)
// ---------------------------------------------------------------------------
__device__ __align__(16) __nv_bfloat16 g_xhi[(size_t)N_BATCH * KP];
__device__ __align__(16) __nv_bfloat16 g_wb [(size_t)N_HID   * KP];
__device__ __align__(16) uint8_t       g_xl8[(size_t)N_BATCH * KP]; // (x-hi)*512 e4m3
__device__ __align__(16) uint8_t       g_w8 [(size_t)N_HID   * KP]; // sign(W) e4m3
// partials: [64 m-blocks][64 n-chunks of 64 cols][128 rows][10 outs]
__device__ float g_part[(size_t)64 * 64 * 128 * N_OUT];

// ---------------------------------------------------------------------------
// Helpers (base sm_103-legal: cp.async, ldmatrix, mma.sync bf16 + e4m3)
// ---------------------------------------------------------------------------
__device__ __forceinline__ uint32_t smem_to_u32(const void* smem_ptr) {
    uint32_t addr;
    asm("{ .reg .u64 tmp; cvta.to.shared.u64 tmp, %1; cvt.u32.u64 %0, tmp; }"
        : "=r"(addr) : "l"(smem_ptr));
    return addr;
}

__device__ __forceinline__ void cp_async16(uint32_t saddr, const void* gptr) {
    asm volatile("cp.async.cg.shared.global [%0], [%1], 16;"
                 :: "r"(saddr), "l"(gptr));
}
#define CP_COMMIT() asm volatile("cp.async.commit_group;" ::: "memory")
#define CP_WAIT(n)  asm volatile("cp.async.wait_group %0;" :: "n"(n) : "memory")

__device__ __forceinline__ void ldsm_x4(uint32_t& r0, uint32_t& r1,
                                        uint32_t& r2, uint32_t& r3,
                                        uint32_t addr) {
    asm volatile("ldmatrix.sync.aligned.m8n8.x4.shared.b16 {%0,%1,%2,%3}, [%4];"
                 : "=r"(r0), "=r"(r1), "=r"(r2), "=r"(r3) : "r"(addr));
}
__device__ __forceinline__ void ldsm_x2(uint32_t& r0, uint32_t& r1,
                                        uint32_t addr) {
    asm volatile("ldmatrix.sync.aligned.m8n8.x2.shared.b16 {%0,%1}, [%2];"
                 : "=r"(r0), "=r"(r1) : "r"(addr));
}

__device__ __forceinline__ void mma_bf16(float* c, const uint32_t* a,
                                         const uint32_t* b) {
    asm volatile(
        "mma.sync.aligned.m16n8k16.row.col.f32.bf16.bf16.f32 "
        "{%0,%1,%2,%3}, {%4,%5,%6,%7}, {%8,%9}, {%0,%1,%2,%3};"
        : "+f"(c[0]), "+f"(c[1]), "+f"(c[2]), "+f"(c[3])
        : "r"(a[0]), "r"(a[1]), "r"(a[2]), "r"(a[3]), "r"(b[0]), "r"(b[1]));
}

// fp8 e4m3 MMA: K=32 per instruction. Fragment byte-layout matches the
// bf16 k16 fragment byte-for-byte, so the same ldmatrix addressing works.
__device__ __forceinline__ void mma_fp8(float* c, const uint32_t* a,
                                        const uint32_t* b) {
    asm volatile(
        "mma.sync.aligned.m16n8k32.row.col.f32.e4m3.e4m3.f32 "
        "{%0,%1,%2,%3}, {%4,%5,%6,%7}, {%8,%9}, {%0,%1,%2,%3};"
        : "+f"(c[0]), "+f"(c[1]), "+f"(c[2]), "+f"(c[3])
        : "r"(a[0]), "r"(a[1]), "r"(a[2]), "r"(a[3]), "r"(b[0]), "r"(b[1]));
}

__device__ __forceinline__ uint32_t sw128(uint32_t b) {
    return b ^ ((b >> 3) & 0x70);
}

// ---------------------------------------------------------------------------
// Prep kernels: W -> sign in bf16 + e4m3; x -> bf16 hi + e4m3 lo (x-hi)*512
// ---------------------------------------------------------------------------
__global__ void prep_w_kernel(const float* __restrict__ W1) {
    int idx4 = blockIdx.x * blockDim.x + threadIdx.x;
    if (idx4 >= N_HID * KP / 4) return;
    int idx = idx4 * 4;
    int r = idx / KP, k = idx - r * KP;
    __nv_bfloat16 ob[4];
    uint8_t o8[4];
    #pragma unroll
    for (int j = 0; j < 4; j++) {
        float s = 0.0f;
        if (k + j < N_IN) {
            float w = W1[(size_t)r * N_IN + k + j];
            s = (w > 0.f) ? 1.f : ((w < 0.f) ? -1.f : 0.f);
        }
        ob[j] = __float2bfloat16(s);
        o8[j] = __nv_cvt_float_to_fp8(s, __NV_SATFINITE, __NV_E4M3);
    }
    *reinterpret_cast<uint2*>(g_wb + idx) = *reinterpret_cast<uint2*>(ob);
    *reinterpret_cast<uint32_t*>(g_w8 + idx) = *reinterpret_cast<uint32_t*>(o8);
}

__global__ void prep_x_kernel(const float* __restrict__ x) {
    int idx4 = blockIdx.x * blockDim.x + threadIdx.x;
    if (idx4 >= N_BATCH * KP / 4) return;
    int idx = idx4 * 4;
    int r = idx / KP, k = idx - r * KP;
    __nv_bfloat16 hi[4];
    uint8_t lo8[4];
    #pragma unroll
    for (int j = 0; j < 4; j++) {
        float v = (k + j < N_IN) ? x[(size_t)r * N_IN + k + j] : 0.0f;
        hi[j] = __float2bfloat16(v);
        float lo = (v - __bfloat162float(hi[j])) * 512.0f;
        lo8[j] = __nv_cvt_float_to_fp8(lo, __NV_SATFINITE, __NV_E4M3);
    }
    *reinterpret_cast<uint2*>(g_xhi + idx) = *reinterpret_cast<uint2*>(hi);
    *reinterpret_cast<uint32_t*>(g_xl8 + idx) = *reinterpret_cast<uint32_t*>(lo8);
}

// ---------------------------------------------------------------------------
// Fused GEMM1 (+bias, clip) + partial GEMM2 kernel
// Grid: (32 n-blocks of 128, 64 m-blocks of 128), 256 threads/CTA
// CTA tile 128x128, warps 2(M) x 4(N), warp tile 64x32.
// hi: bf16 m16n8k16 (8 k-steps / big chunk); lo: e4m3 m16n8k32 (4 k-steps).
// ---------------------------------------------------------------------------
#define SMEM_B1     0                    // 128 floats
#define SMEM_W2     512                  // 1280 floats [512, 5632)
#define SMEM_T0     8192
#define STG_AH      0                    // 32 KB: 2 sub-tiles of 16 KB
#define STG_BH      32768                // 32 KB
#define STG_AL      65536                // 16 KB
#define STG_BL      81920                // 16 KB
#define STG_SIZE    98304
#define SMEM_T1     (SMEM_T0 + STG_SIZE)
#define SMEM_H      SMEM_T0              // h tile 128*132*4 = 67584 B
#define SMEM_TOTAL  (SMEM_T0 + 2 * STG_SIZE)   // 204800 B

__global__ void __launch_bounds__(256)
gemm_fused_kernel(const float* __restrict__ b1, const float* __restrict__ W2)
{
    extern __shared__ char smem[];
    const uint32_t smem_base = smem_to_u32(smem);
    const int tid = threadIdx.x;
    const int wid = tid >> 5;
    const int lid = tid & 31;
    const int nb  = blockIdx.x;       // n-block: 128 hidden cols
    const int mb  = blockIdx.y;       // m-block: 128 batch rows
    const int nbase = nb * 128;

    {
        float* b1s = reinterpret_cast<float*>(smem + SMEM_B1);
        float* w2s = reinterpret_cast<float*>(smem + SMEM_W2);
        if (tid < 128) b1s[tid] = b1[nbase + tid];
        for (int i = tid; i < N_OUT * 128; i += 256) {
            int o = i >> 7, n = i & 127;
            w2s[i] = W2[(size_t)o * N_HID + nbase + n];
        }
    }

    const __nv_bfloat16* Ah = g_xhi + (size_t)mb * 128 * KP;
    const __nv_bfloat16* Bh = g_wb  + (size_t)nbase * KP;
    const uint8_t*       Al = g_xl8 + (size_t)mb * 128 * KP;
    const uint8_t*       Bl = g_w8  + (size_t)nbase * KP;

    // load one 96 KB big-chunk (128 k-elements)
    auto load_chunk = [&](int kc, uint32_t stage) {
        const int kco = kc * 128;   // element offset
        #pragma unroll
        for (int t = tid; t < 128 * 8; t += 256) {
            int r = t >> 3, i = t & 7;
            uint32_t so = sw128((r << 7) | (i << 4));
            // bf16 hi: 2 sub-tiles of 64 k-elements (128 B rows)
            cp_async16(stage + STG_AH + so,
                       Ah + (size_t)r * KP + kco + i * 8);
            cp_async16(stage + STG_AH + 16384 + so,
                       Ah + (size_t)r * KP + kco + 64 + i * 8);
            cp_async16(stage + STG_BH + so,
                       Bh + (size_t)r * KP + kco + i * 8);
            cp_async16(stage + STG_BH + 16384 + so,
                       Bh + (size_t)r * KP + kco + 64 + i * 8);
            // fp8 lo: 128 k-bytes per row
            cp_async16(stage + STG_AL + so,
                       Al + (size_t)r * KP + kco + i * 16);
            cp_async16(stage + STG_BL + so,
                       Bl + (size_t)r * KP + kco + i * 16);
        }
    };

    const int wm = wid >> 2;    // 0..1 (M: 64 rows)
    const int wn = wid & 3;     // 0..3 (N: 32 cols)

    float chi[16][4], clo[16][4];
    #pragma unroll
    for (int t = 0; t < 16; t++)
        #pragma unroll
        for (int a = 0; a < 4; a++) { chi[t][a] = 0.0f; clo[t][a] = 0.0f; }

    load_chunk(0, smem_base + SMEM_T0);
    CP_COMMIT();

    const uint32_t a_row = (uint32_t)(lid & 15);
    const uint32_t a_byt = (uint32_t)((lid >> 4) << 4);
    const uint32_t b_row = (uint32_t)(lid & 7);
    const uint32_t b_byt = (uint32_t)(((lid >> 3) & 1) << 4);

    // one bf16 k16-step on a 128B-row sub-tile
    auto hi_step = [&](uint32_t sa, uint32_t sb, int s) {
        const uint32_t kbyt = s * 32;
        uint32_t bfr[4][2];
        #pragma unroll
        for (int j = 0; j < 4; j++) {
            uint32_t nrow = wn * 32 + j * 8 + b_row;
            ldsm_x2(bfr[j][0], bfr[j][1], sb + sw128((nrow << 7) + kbyt + b_byt));
        }
        #pragma unroll
        for (int i = 0; i < 4; i++) {
            uint32_t af[4];
            uint32_t arow = wm * 64 + i * 16 + a_row;
            ldsm_x4(af[0], af[1], af[2], af[3],
                    sa + sw128((arow << 7) + kbyt + a_byt));
            #pragma unroll
            for (int j = 0; j < 4; j++) mma_bf16(chi[i * 4 + j], af, bfr[j]);
        }
    };

    // one e4m3 k32-step on a 128B-row fp8 tile (same addressing!)
    auto lo_step = [&](uint32_t sa, uint32_t sb, int s) {
        const uint32_t kbyt = s * 32;
        uint32_t bfr[4][2];
        #pragma unroll
        for (int j = 0; j < 4; j++) {
            uint32_t nrow = wn * 32 + j * 8 + b_row;
            ldsm_x2(bfr[j][0], bfr[j][1], sb + sw128((nrow << 7) + kbyt + b_byt));
        }
        #pragma unroll
        for (int i = 0; i < 4; i++) {
            uint32_t af[4];
            uint32_t arow = wm * 64 + i * 16 + a_row;
            ldsm_x4(af[0], af[1], af[2], af[3],
                    sa + sw128((arow << 7) + kbyt + a_byt));
            #pragma unroll
            for (int j = 0; j < 4; j++) mma_fp8(clo[i * 4 + j], af, bfr[j]);
        }
    };

    for (int kc = 0; kc < NCH; kc++) {
        if (kc + 1 < NCH) {
            load_chunk(kc + 1, smem_base + ((kc + 1) & 1 ? SMEM_T1 : SMEM_T0));
            CP_COMMIT();
            CP_WAIT(1);
        } else {
            CP_WAIT(0);
        }
        __syncthreads();

        const uint32_t stage = smem_base + ((kc & 1) ? SMEM_T1 : SMEM_T0);

        if (kc == NCH - 1) {
            // only k 768..783 real: 1 hi k16-step, 1 lo k32-step
            hi_step(stage + STG_AH, stage + STG_BH, 0);
            lo_step(stage + STG_AL, stage + STG_BL, 0);
        } else {
            #pragma unroll
            for (int s2 = 0; s2 < 2; s2++)
                #pragma unroll
                for (int s = 0; s < 4; s++)
                    hi_step(stage + STG_AH + s2 * 16384,
                            stage + STG_BH + s2 * 16384, s);
            #pragma unroll
            for (int s = 0; s < 4; s++)
                lo_step(stage + STG_AL, stage + STG_BL, s);
        }
        __syncthreads();
    }

    // ---- epilogue: combine hi + lo/512, +b1, clip -> h tile (stride 132) ---
    {
        const float* b1s = reinterpret_cast<const float*>(smem + SMEM_B1);
        float* hs = reinterpret_cast<float*>(smem + SMEM_H);
        const float is = 1.0f / 512.0f;
        #pragma unroll
        for (int i = 0; i < 4; i++) {
            #pragma unroll
            for (int j = 0; j < 4; j++) {
                int r0 = wm * 64 + i * 16 + (lid >> 2);
                int cc = wn * 32 + j * 8 + (lid & 3) * 2;
                float bb0 = b1s[cc], bb1 = b1s[cc + 1];
                int t = i * 4 + j;
                float v0 = chi[t][0] + clo[t][0] * is + bb0;
                float v1 = chi[t][1] + clo[t][1] * is + bb1;
                float v2 = chi[t][2] + clo[t][2] * is + bb0;
                float v3 = chi[t][3] + clo[t][3] * is + bb1;
                v0 = fminf(1.f, fmaxf(-1.f, v0));
                v1 = fminf(1.f, fmaxf(-1.f, v1));
                v2 = fminf(1.f, fmaxf(-1.f, v2));
                v3 = fminf(1.f, fmaxf(-1.f, v3));
                hs[r0 * 132 + cc]           = v0;
                hs[r0 * 132 + cc + 1]       = v1;
                hs[(r0 + 8) * 132 + cc]     = v2;
                hs[(r0 + 8) * 132 + cc + 1] = v3;
            }
        }
    }
    __syncthreads();

    // ---- partial GEMM2: thread = (row, half of 64 cols) -> g_part ----
    {
        const int row  = tid >> 1;
        const int half = tid & 1;
        const float* hrow =
            reinterpret_cast<const float*>(smem + SMEM_H) + row * 132 + half * 64;
        const float* w2s =
            reinterpret_cast<const float*>(smem + SMEM_W2) + half * 64;

        float acc[N_OUT];
        #pragma unroll
        for (int o = 0; o < N_OUT; o++) acc[o] = 0.0f;
        #pragma unroll 8
        for (int cidx = 0; cidx < 64; cidx++) {
            float h = hrow[cidx];
            #pragma unroll
            for (int o = 0; o < N_OUT; o++) acc[o] += h * w2s[o * 128 + cidx];
        }
        const size_t pb =
            ((size_t)(mb * 64 + nb * 2 + half) * 128 + row) * N_OUT;
        #pragma unroll
        for (int o = 0; o < N_OUT; o++) g_part[pb + o] = acc[o];
    }
}

// ---------------------------------------------------------------------------
// Final reduce: out[m,o] = b2[o] + sum over 64 n-chunks of partials
// ---------------------------------------------------------------------------
__global__ void reduce_kernel(const float* __restrict__ b2,
                              float* __restrict__ out)
{
    int idx = blockIdx.x * blockDim.x + threadIdx.x;
    if (idx >= N_BATCH * N_OUT) return;
    int m = idx / N_OUT, o = idx - m * N_OUT;
    int mb = m >> 7, r = m & 127;
    float s = b2[o];
    const float* p = g_part + ((size_t)(mb * 64) * 128 + r) * N_OUT + o;
    #pragma unroll
    for (int nc = 0; nc < 64; nc++) s += p[(size_t)nc * 128 * N_OUT];
    out[idx] = s;
}

// ---------------------------------------------------------------------------
// kernel_launch
// ---------------------------------------------------------------------------
extern "C" void kernel_launch(void* const* d_in, const int* in_sizes, int n_in,
                              void* d_out, int out_size)
{
    const float* x  = (const float*)d_in[0];
    const float* W1 = (const float*)d_in[1];
    const float* b1 = (const float*)d_in[2];
    const float* W2 = (const float*)d_in[3];
    const float* b2 = (const float*)d_in[4];
    float* out = (float*)d_out;

    cudaFuncSetAttribute(gemm_fused_kernel,
                         cudaFuncAttributeMaxDynamicSharedMemorySize, SMEM_TOTAL);

    prep_x_kernel<<<(N_BATCH * KP / 4 + 255) / 256, 256>>>(x);
    prep_w_kernel<<<(N_HID * KP / 4 + 255) / 256, 256>>>(W1);
    gemm_fused_kernel<<<dim3(32, 64), 256, SMEM_TOTAL>>>(b1, W2);
    reduce_kernel<<<(N_BATCH * N_OUT + 255) / 256, 256>>>(b2, out);
}